// round 8
// baseline (speedup 1.0000x reference)
#include <cuda_runtime.h>
#include <math.h>
#include <stdint.h>

#define BB 128
#define SS 512
#define VV 6000
#define EE 100
#define HH 256
#define TT 9
#define NBLK 128

__device__ float g_P[2][VV][1024];       // token projection, col = 4*u + gate(i,f,g,o)
__device__ float g_hcur[2][2][BB][HH];   // [parity][dir][b][u]
__device__ float g_hall[(size_t)SS * BB * 512]; // [s][b][dir*256+u]
__device__ float g_em[(size_t)BB * SS * TT];    // [b][s][t]
__device__ unsigned g_bar_count = 0;
__device__ unsigned g_bar_gen = 0;

__device__ __forceinline__ float sigf(float x) { return 1.0f / (1.0f + expf(-x)); }

__device__ __forceinline__ void grid_barrier() {
  __syncthreads();
  if (threadIdx.x == 0) {
    __threadfence();
    unsigned gen = *((volatile unsigned*)&g_bar_gen);
    unsigned old = atomicAdd(&g_bar_count, 1u);
    if (old == NBLK - 1) {
      *((volatile unsigned*)&g_bar_count) = 0;
      __threadfence();
      atomicAdd(&g_bar_gen, 1u);
    } else {
      while (*((volatile unsigned*)&g_bar_gen) == gen) __nanosleep(64);
    }
    __threadfence();
  }
  __syncthreads();
}

// ---------- kernel 1: P[dir][v][c] = emb[v] @ W_ih^T + b  (c = u*4+gate) ----
// grid: 375 vt * 4 ct * 2 dir = 3000 blocks, 256 threads. smem 108800 B.
__global__ __launch_bounds__(256) void proj_kernel(
    const float* __restrict__ emb,
    const float* __restrict__ Wf, const float* __restrict__ bf,
    const float* __restrict__ Wb, const float* __restrict__ bb2) {
  extern __shared__ float sm[];
  float* Ws = sm;            // [EE][256]
  float* Es = sm + EE * 256; // [EE][16]
  int id = blockIdx.x;
  int dir = id & 1; id >>= 1;
  int ct = id & 3;  id >>= 2;
  int vt = id;
  const float* W = dir ? Wb : Wf;
  const float* bias = dir ? bb2 : bf;
  int tid = threadIdx.x;
  // coalesced load of W slice, transposed into Ws[e*256 + u*4+g]
  for (int idx = tid; idx < 4 * 64 * EE; idx += 256) {
    int g = idx / (64 * EE);
    int rem = idx - g * 64 * EE;
    int u = rem / EE;
    int e = rem - u * EE;
    Ws[e * 256 + u * 4 + g] = W[(g * HH + ct * 64 + u) * EE + e];
  }
  for (int idx = tid; idx < 16 * EE; idx += 256) {
    int v = idx / EE, e = idx - v * EE;
    Es[e * 16 + v] = emb[(vt * 16 + v) * EE + e];
  }
  __syncthreads();

  int vg = tid & 3, cg = tid >> 2;
  float acc[4][4];
#pragma unroll
  for (int i = 0; i < 4; i++)
#pragma unroll
    for (int j = 0; j < 4; j++) acc[i][j] = 0.f;
  for (int e = 0; e < EE; e++) {
    float4 ev = *(const float4*)&Es[e * 16 + vg * 4];
    float4 wv = *(const float4*)&Ws[e * 256 + cg * 4];
    float eh[4] = {ev.x, ev.y, ev.z, ev.w};
    float wh[4] = {wv.x, wv.y, wv.z, wv.w};
#pragma unroll
    for (int i = 0; i < 4; i++)
#pragma unroll
      for (int j = 0; j < 4; j++) acc[i][j] += eh[i] * wh[j];
  }
  int colb = ct * 256 + cg * 4;
  int u = colb >> 2;
  float bi[4] = {bias[u], bias[HH + u], bias[2 * HH + u], bias[3 * HH + u]};
  int vbase = vt * 16 + vg * 4;
#pragma unroll
  for (int i = 0; i < 4; i++) {
    float4 o = make_float4(acc[i][0] + bi[0], acc[i][1] + bi[1],
                           acc[i][2] + bi[2], acc[i][3] + bi[3]);
    *(float4*)&g_P[dir][vbase + i][colb] = o;
  }
}

// ---------- kernel 2: persistent bidirectional LSTM -------------------------
// 128 blocks x 128 threads: dir(2) x batch-chunk(8 of 16) x hidden-chunk(8 of 32)
// smem 147456 B dynamic.
__global__ __launch_bounds__(128) void lstm_kernel(
    const int* __restrict__ data,
    const float* __restrict__ Whh_f, const float* __restrict__ Whh_b) {
  extern __shared__ float sm[];
  float* wT = sm;             // [k=256][row=128], row = u_local*4 + gate
  float* hT = sm + 256 * 128; // [k=256][b_local=16]
  __shared__ int tok_s[16];

  int tid = threadIdx.x;
  int bid = blockIdx.x;
  int dir = bid >> 6;
  int r = bid & 63;
  int bc = r >> 3;
  int hc = r & 7;
  const float* Whh = dir ? Whh_b : Whh_f;

  // load W_hh slice transposed, coalesced over k
  for (int ri = 0; ri < 128; ri++) {
    int u = ri >> 2, g = ri & 3;
    const float* row = Whh + (g * HH + hc * 32 + u) * HH;
    for (int k = tid; k < HH; k += 128) wT[k * 128 + ri] = row[k];
  }

  int bg = tid & 3;
  int ug = tid >> 2;
  int uglob = hc * 32 + ug;
  int colbase = uglob * 4;
  float cst[4] = {0.f, 0.f, 0.f, 0.f};
#pragma unroll
  for (int i = 0; i < 4; i++) g_hcur[0][dir][bc * 16 + bg * 4 + i][uglob] = 0.f;

  const float* hp = hT + bg * 4;
  const float* wp = wT + ug * 4;

  for (int t = 0; t < SS; t++) {
    grid_barrier();
    int par = t & 1, np = par ^ 1;
    int s = dir ? (SS - 1 - t) : t;

    const float* hsrc = &g_hcur[par][dir][bc * 16][0];
    for (int idx = tid; idx < 16 * 64; idx += 128) {
      int b = idx >> 6, k4 = idx & 63;
      float4 v = *(const float4*)&hsrc[b * HH + k4 * 4];
      hT[(k4 * 4 + 0) * 16 + b] = v.x;
      hT[(k4 * 4 + 1) * 16 + b] = v.y;
      hT[(k4 * 4 + 2) * 16 + b] = v.z;
      hT[(k4 * 4 + 3) * 16 + b] = v.w;
    }
    if (tid < 16) tok_s[tid] = data[(bc * 16 + tid) * SS + s];
    __syncthreads();

    float acc[4][4];
#pragma unroll
    for (int i = 0; i < 4; i++) {
      float4 p = *(const float4*)&g_P[dir][tok_s[bg * 4 + i]][colbase];
      acc[i][0] = p.x; acc[i][1] = p.y; acc[i][2] = p.z; acc[i][3] = p.w;
    }
#pragma unroll 8
    for (int k = 0; k < HH; k++) {
      float4 h4 = *(const float4*)(hp + k * 16);
      float4 w4 = *(const float4*)(wp + k * 128);
      float hh[4] = {h4.x, h4.y, h4.z, h4.w};
      float ww[4] = {w4.x, w4.y, w4.z, w4.w};
#pragma unroll
      for (int i = 0; i < 4; i++)
#pragma unroll
        for (int g = 0; g < 4; g++) acc[i][g] += hh[i] * ww[g];
    }
#pragma unroll
    for (int i = 0; i < 4; i++) {
      float ii = sigf(acc[i][0]), ff = sigf(acc[i][1]);
      float gg = tanhf(acc[i][2]), oo = sigf(acc[i][3]);
      cst[i] = ff * cst[i] + ii * gg;
      float hv = oo * tanhf(cst[i]);
      int bgl = bc * 16 + bg * 4 + i;
      g_hcur[np][dir][bgl][uglob] = hv;
      g_hall[((size_t)s * BB + bgl) * 512 + dir * HH + uglob] = hv;
    }
  }
}

// ---------- kernel 3: emissions em[b][s][t] = h[s][b] . mlp_W[t] + mlp_b ----
__global__ __launch_bounds__(128) void emis_kernel(
    const float* __restrict__ mlpW, const float* __restrict__ mlpb) {
  __shared__ float Ws[TT * 512];
  int s = blockIdx.x, b = threadIdx.x;
  for (int i = threadIdx.x; i < TT * 512; i += 128) Ws[i] = mlpW[i];
  __syncthreads();
  float acc[TT];
#pragma unroll
  for (int t = 0; t < TT; t++) acc[t] = mlpb[t];
  const float* hr = g_hall + ((size_t)s * BB + b) * 512;
  for (int h = 0; h < 512; h += 4) {
    float4 hv = *(const float4*)(hr + h);
#pragma unroll
    for (int t = 0; t < TT; t++) {
      const float* w = Ws + t * 512 + h;
      acc[t] += hv.x * w[0] + hv.y * w[1] + hv.z * w[2] + hv.w * w[3];
    }
  }
#pragma unroll
  for (int t = 0; t < TT; t++) g_em[((size_t)b * 512 + s) * TT + t] = acc[t];
}

// ---------- kernel 4: Viterbi, one warp per batch ---------------------------
__global__ __launch_bounds__(32) void vit_kernel(
    const int* __restrict__ data,
    const float* __restrict__ start_t, const float* __restrict__ trans,
    const float* __restrict__ end_t, float* __restrict__ out) {
  __shared__ unsigned char bp[SS * TT];
  __shared__ unsigned char msk[SS];
  int b = blockIdx.x, j = threadIdx.x;
  bool act = (j < TT);
  const float* em = g_em + (size_t)b * SS * TT;
  float tr[TT];
#pragma unroll
  for (int i = 0; i < TT; i++) tr[i] = act ? trans[i * TT + j] : 0.f;
  float score = act ? (start_t[j] + em[j]) : -1e30f;
  if (j == 0) msk[0] = (data[b * SS] != 0);

  for (int s = 1; s < SS; s++) {
    float e = act ? em[s * TT + j] : 0.f;
    bool m = (data[b * SS + s] != 0);
    float best = -1e30f; int arg = 0;
#pragma unroll
    for (int i = 0; i < TT; i++) {
      float si = __shfl_sync(0xffffffffu, score, i);
      float cand = (si + tr[i]) + e;   // reference op order
      if (cand > best) { best = cand; arg = i; }  // first-max
    }
    if (act && m) score = best;
    if (act) bp[s * TT + j] = (unsigned char)arg;
    if (j == 0) msk[s] = m ? 1 : 0;
  }

  float fin = act ? (score + end_t[j]) : -1e30f;
  float bestf = -1e30f; int tag = 0;
#pragma unroll
  for (int i = 0; i < TT; i++) {
    float v = __shfl_sync(0xffffffffu, fin, i);
    if (v > bestf) { bestf = v; tag = i; }
  }
  __syncwarp();
  if (j == 0) {
    out[BB * SS + b] = bestf;
    for (int s = SS - 1; s >= 1; s--) {
      out[b * SS + s] = msk[s] ? (float)tag : 0.f;
      if (msk[s]) tag = bp[s * TT + tag];
    }
    out[b * SS] = msk[0] ? (float)tag : 0.f;
  }
}

extern "C" void kernel_launch(void* const* d_in, const int* in_sizes, int n_in,
                              void* d_out, int out_size) {
  (void)in_sizes; (void)n_in; (void)out_size;
  const int* data = (const int*)d_in[0];
  // d_in[1] = mask (ignored: mask == (data != 0) exactly)
  const float* emb   = (const float*)d_in[2];
  const float* Wih_f = (const float*)d_in[3];
  const float* Whh_f = (const float*)d_in[4];
  const float* b_f   = (const float*)d_in[5];
  const float* Wih_b = (const float*)d_in[6];
  const float* Whh_b = (const float*)d_in[7];
  const float* b_b   = (const float*)d_in[8];
  const float* mlpW  = (const float*)d_in[9];
  const float* mlpb  = (const float*)d_in[10];
  const float* st    = (const float*)d_in[11];
  const float* tr    = (const float*)d_in[12];
  const float* et    = (const float*)d_in[13];
  float* out = (float*)d_out;

  size_t proj_smem = (size_t)(EE * 256 + EE * 16) * 4;   // 108800
  size_t lstm_smem = (size_t)(256 * 128 + 256 * 16) * 4; // 147456
  cudaFuncSetAttribute(proj_kernel, cudaFuncAttributeMaxDynamicSharedMemorySize, (int)proj_smem);
  cudaFuncSetAttribute(lstm_kernel, cudaFuncAttributeMaxDynamicSharedMemorySize, (int)lstm_smem);

  proj_kernel<<<3000, 256, proj_smem>>>(emb, Wih_f, b_f, Wih_b, b_b);
  lstm_kernel<<<NBLK, 128, lstm_smem>>>(data, Whh_f, Whh_b);
  emis_kernel<<<SS, 128>>>(mlpW, mlpb);
  vit_kernel<<<BB, 32>>>(data, st, tr, et, out);
}

// round 11
// speedup vs baseline: 1.2737x; 1.2737x over previous
#include <cuda_runtime.h>
#include <math.h>
#include <stdint.h>

#define BB 128
#define SS 512
#define VV 6000
#define EE 100
#define HH 256
#define TT 9
#define NBLK 128

typedef unsigned long long u64;

__device__ float g_P[2][VV][1024];            // token projection, col = u*4 + gate(i,f,g,o)
__device__ float g_hT[2][2][8][256][16];      // [parity][dir][bc][u][b_local] transposed h
__device__ float g_hall[(size_t)SS * 2 * HH * BB]; // [s][dir][u][b]
__device__ float g_em[(size_t)BB * SS * TT];  // [b][s][t]
__device__ unsigned g_bar_count = 0;
__device__ unsigned g_bar_gen = 0;

__device__ __forceinline__ float sigf(float x) { return 1.0f / (1.0f + expf(-x)); }
__device__ __forceinline__ u64 dupf(float x) {
  unsigned b = __float_as_uint(x);
  return ((u64)b << 32) | (u64)b;
}
__device__ __forceinline__ float lo32(u64 v) { return __uint_as_float((unsigned)v); }
__device__ __forceinline__ float hi32(u64 v) { return __uint_as_float((unsigned)(v >> 32)); }
#define FMA2(d, a, b) asm("fma.rn.f32x2 %0, %1, %2, %0;" : "+l"(d) : "l"(a), "l"(b))

__device__ __forceinline__ void grid_barrier() {
  __syncthreads();
  if (threadIdx.x == 0) {
    __threadfence();
    unsigned gen = *((volatile unsigned*)&g_bar_gen);
    unsigned old = atomicAdd(&g_bar_count, 1u);
    if (old == NBLK - 1) {
      *((volatile unsigned*)&g_bar_count) = 0;
      __threadfence();
      atomicAdd(&g_bar_gen, 1u);
    } else {
      while (*((volatile unsigned*)&g_bar_gen) == gen) {}
    }
    __threadfence();
  }
  __syncthreads();
}

// ---------- kernel 1: P[dir][v][c] = emb[v] @ W_ih^T + b  (c = u*4+gate) ----
__global__ __launch_bounds__(256) void proj_kernel(
    const float* __restrict__ emb,
    const float* __restrict__ Wf, const float* __restrict__ bf,
    const float* __restrict__ Wb, const float* __restrict__ bb2) {
  extern __shared__ float sm[];
  float* Ws = sm;            // [EE][256]
  float* Es = sm + EE * 256; // [EE][16]
  int id = blockIdx.x;
  int dir = id & 1; id >>= 1;
  int ct = id & 3;  id >>= 2;
  int vt = id;
  const float* W = dir ? Wb : Wf;
  const float* bias = dir ? bb2 : bf;
  int tid = threadIdx.x;
  for (int idx = tid; idx < 4 * 64 * EE; idx += 256) {
    int g = idx / (64 * EE);
    int rem = idx - g * 64 * EE;
    int u = rem / EE;
    int e = rem - u * EE;
    Ws[e * 256 + u * 4 + g] = W[(g * HH + ct * 64 + u) * EE + e];
  }
  for (int idx = tid; idx < 16 * EE; idx += 256) {
    int v = idx / EE, e = idx - v * EE;
    Es[e * 16 + v] = emb[(vt * 16 + v) * EE + e];
  }
  __syncthreads();

  int vg = tid & 3, cg = tid >> 2;
  float acc[4][4];
#pragma unroll
  for (int i = 0; i < 4; i++)
#pragma unroll
    for (int j = 0; j < 4; j++) acc[i][j] = 0.f;
  for (int e = 0; e < EE; e++) {
    float4 ev = *(const float4*)&Es[e * 16 + vg * 4];
    float4 wv = *(const float4*)&Ws[e * 256 + cg * 4];
    float eh[4] = {ev.x, ev.y, ev.z, ev.w};
    float wh[4] = {wv.x, wv.y, wv.z, wv.w};
#pragma unroll
    for (int i = 0; i < 4; i++)
#pragma unroll
      for (int j = 0; j < 4; j++) acc[i][j] += eh[i] * wh[j];
  }
  int colb = ct * 256 + cg * 4;
  int u = colb >> 2;
  float bi[4] = {bias[u], bias[HH + u], bias[2 * HH + u], bias[3 * HH + u]};
  int vbase = vt * 16 + vg * 4;
#pragma unroll
  for (int i = 0; i < 4; i++) {
    float4 o = make_float4(acc[i][0] + bi[0], acc[i][1] + bi[1],
                           acc[i][2] + bi[2], acc[i][3] + bi[3]);
    *(float4*)&g_P[dir][vbase + i][colb] = o;
  }
}

// ---------- kernel 2: persistent bidirectional LSTM -------------------------
// 128 blocks x 256 threads: dir(2) x batch-chunk(8 of 16) x hidden-chunk(8 of 32)
// thread: bg = tid&7 (batches 2bg,2bg+1), ug = tid>>3 (unit). smem 163840 B.
__global__ __launch_bounds__(256) void lstm_kernel(
    const int* __restrict__ data,
    const float* __restrict__ Whh_f, const float* __restrict__ Whh_b) {
  extern __shared__ float sm[];
  float* wT = sm;                       // [k=256][u*4+gate] floats (= u64 pairs)
  u64* hT2 = (u64*)(sm + 256 * 128);    // [k=256][b=16] duplicated (h,h)
  __shared__ int toks[2][16];

  int tid = threadIdx.x;
  int bid = blockIdx.x;
  int dir = bid >> 6;
  int r = bid & 63;
  int bc = r >> 3;
  int hc = r & 7;
  const float* Whh = dir ? Whh_b : Whh_f;

  // load W_hh slice transposed, coalesced over k
  for (int ri = tid >> 4; ri < 128; ri += 16) {  // 16 rows in parallel
    int u = ri >> 2, g = ri & 3;
    const float* row = Whh + (g * HH + hc * 32 + u) * HH;
    for (int k = (tid & 15); k < HH; k += 16) wT[k * 128 + ri] = row[k];
  }

  int bg = tid & 7;          // batch pair
  int ug = tid >> 3;         // local unit 0..31
  int uglob = hc * 32 + ug;
  int colbase = uglob * 4;
  int b0 = bc * 16 + 2 * bg; // global batch of first of pair
  float c0 = 0.f, c1 = 0.f;

  // zero-init h parity-0 buffer for owned cells
  *(float2*)&g_hT[0][dir][bc][uglob][2 * bg] = make_float2(0.f, 0.f);

  // initial tokens + P prefetch for t=0
  int s0 = dir ? (SS - 1) : 0;
  if (tid < 16) toks[0][tid] = data[(bc * 16 + tid) * SS + s0];
  __syncthreads();
  ulonglong2 pf0 = *(const ulonglong2*)&g_P[dir][toks[0][2 * bg + 0]][colbase];
  ulonglong2 pf1 = *(const ulonglong2*)&g_P[dir][toks[0][2 * bg + 1]][colbase];

  const u64* hB = hT2 + 2 * bg;
  const float* wB = wT + ug * 4;

  for (int t = 0; t < SS; t++) {
    grid_barrier();
    int par = t & 1, np = par ^ 1, nb = (t + 1) & 1;
    int s = dir ? (SS - 1 - t) : t;
    int s_next = dir ? (SS - 2 - t) : (t + 1);
    if (t == SS - 1) s_next = s;  // harmless clamp

    // copy h tile -> duplicated smem pairs (straight layout, no scatter)
    {
      const float4* src = (const float4*)&g_hT[par][dir][bc][0][0];
#pragma unroll
      for (int i = 0; i < 4; i++) {
        float4 v = src[tid + i * 256];
        int e = (tid + i * 256) * 4;
        ulonglong2 d0; d0.x = dupf(v.x); d0.y = dupf(v.y);
        ulonglong2 d1; d1.x = dupf(v.z); d1.y = dupf(v.w);
        *(ulonglong2*)&hT2[e] = d0;
        *(ulonglong2*)&hT2[e + 2] = d1;
      }
      if (tid < 16) toks[nb][tid] = data[(bc * 16 + tid) * SS + s_next];
    }
    __syncthreads();

    // accumulators from prefetched P (pairs: (i,f) and (g,o))
    u64 a0a = pf0.x, a0b = pf0.y;
    u64 a1a = pf1.x, a1b = pf1.y;

#pragma unroll 8
    for (int k = 0; k < HH; k++) {
      ulonglong2 hh = *(const ulonglong2*)(hB + k * 16);
      ulonglong2 ww = *(const ulonglong2*)(wB + k * 128);
      FMA2(a0a, hh.x, ww.x);
      FMA2(a0b, hh.x, ww.y);
      FMA2(a1a, hh.y, ww.x);
      FMA2(a1b, hh.y, ww.y);
    }

    // epilogue: LSTM cell for the 2 batches
    float h0, h1;
    {
      float gi = sigf(lo32(a0a)), gf = sigf(hi32(a0a));
      float gg = tanhf(lo32(a0b)), go = sigf(hi32(a0b));
      c0 = gf * c0 + gi * gg;
      h0 = go * tanhf(c0);
    }
    {
      float gi = sigf(lo32(a1a)), gf = sigf(hi32(a1a));
      float gg = tanhf(lo32(a1b)), go = sigf(hi32(a1b));
      c1 = gf * c1 + gi * gg;
      h1 = go * tanhf(c1);
    }
    *(float2*)&g_hT[np][dir][bc][uglob][2 * bg] = make_float2(h0, h1);
    *(float2*)&g_hall[(((size_t)s * 2 + dir) * HH + uglob) * BB + b0] = make_float2(h0, h1);

    // prefetch P for next step (toks[nb] written before this step's syncthreads)
    pf0 = *(const ulonglong2*)&g_P[dir][toks[nb][2 * bg + 0]][colbase];
    pf1 = *(const ulonglong2*)&g_P[dir][toks[nb][2 * bg + 1]][colbase];
  }
}

// ---------- kernel 3: emissions em[b][s][t] = h . mlp_W[t] + mlp_b ---------
__global__ __launch_bounds__(128) void emis_kernel(
    const float* __restrict__ mlpW, const float* __restrict__ mlpb) {
  __shared__ float Ws[TT * 512];
  int s = blockIdx.x, b = threadIdx.x;
  for (int i = threadIdx.x; i < TT * 512; i += 128) Ws[i] = mlpW[i];
  __syncthreads();
  float acc[TT];
#pragma unroll
  for (int t = 0; t < TT; t++) acc[t] = mlpb[t];
  const float* hr = g_hall + (size_t)s * 512 * BB + b;  // [c][b] rows, coalesced over b
#pragma unroll 4
  for (int c = 0; c < 512; c++) {
    float hv = hr[(size_t)c * BB];
#pragma unroll
    for (int t = 0; t < TT; t++) acc[t] += hv * Ws[t * 512 + c];
  }
#pragma unroll
  for (int t = 0; t < TT; t++) g_em[((size_t)b * SS + s) * TT + t] = acc[t];
}

// ---------- kernel 4: Viterbi, one warp per batch, prefetched --------------
__global__ __launch_bounds__(32) void vit_kernel(
    const int* __restrict__ data,
    const float* __restrict__ start_t, const float* __restrict__ trans,
    const float* __restrict__ end_t, float* __restrict__ out) {
  __shared__ unsigned char bp[SS * TT];
  __shared__ unsigned char msk[SS];
  int b = blockIdx.x, j = threadIdx.x;
  bool act = (j < TT);
  const float* em = g_em + (size_t)b * SS * TT;
  const int* db = data + b * SS;
  float tr[TT];
#pragma unroll
  for (int i = 0; i < TT; i++) tr[i] = act ? trans[i * TT + j] : 0.f;
  float score = act ? (start_t[j] + em[j]) : -1e30f;
  if (j == 0) msk[0] = (db[0] != 0);

  float e_cur = act ? em[TT + j] : 0.f;
  int m_cur = db[1];
  for (int s = 1; s < SS; s++) {
    float e_nxt = 0.f; int m_nxt = 0;
    if (s + 1 < SS) {
      e_nxt = act ? em[(s + 1) * TT + j] : 0.f;
      m_nxt = db[s + 1];
    }
    float best = -1e30f; int arg = 0;
#pragma unroll
    for (int i = 0; i < TT; i++) {
      float si = __shfl_sync(0xffffffffu, score, i);
      float cand = (si + tr[i]) + e_cur;        // reference op order
      if (cand > best) { best = cand; arg = i; } // first-max
    }
    if (act && m_cur != 0) score = best;
    if (act) bp[s * TT + j] = (unsigned char)arg;
    if (j == 0) msk[s] = (m_cur != 0) ? 1 : 0;
    e_cur = e_nxt; m_cur = m_nxt;
  }

  float fin = act ? (score + end_t[j]) : -1e30f;
  float bestf = -1e30f; int tag = 0;
#pragma unroll
  for (int i = 0; i < TT; i++) {
    float v = __shfl_sync(0xffffffffu, fin, i);
    if (v > bestf) { bestf = v; tag = i; }
  }
  __syncwarp();
  if (j == 0) {
    out[BB * SS + b] = bestf;
    for (int s = SS - 1; s >= 1; s--) {
      out[b * SS + s] = msk[s] ? (float)tag : 0.f;
      if (msk[s]) tag = bp[s * TT + tag];
    }
    out[b * SS] = msk[0] ? (float)tag : 0.f;
  }
}

extern "C" void kernel_launch(void* const* d_in, const int* in_sizes, int n_in,
                              void* d_out, int out_size) {
  (void)in_sizes; (void)n_in; (void)out_size;
  const int* data = (const int*)d_in[0];
  // d_in[1] = mask (ignored: mask == (data != 0) exactly)
  const float* emb   = (const float*)d_in[2];
  const float* Wih_f = (const float*)d_in[3];
  const float* Whh_f = (const float*)d_in[4];
  const float* b_f   = (const float*)d_in[5];
  const float* Wih_b = (const float*)d_in[6];
  const float* Whh_b = (const float*)d_in[7];
  const float* b_b   = (const float*)d_in[8];
  const float* mlpW  = (const float*)d_in[9];
  const float* mlpb  = (const float*)d_in[10];
  const float* st    = (const float*)d_in[11];
  const float* tr    = (const float*)d_in[12];
  const float* et    = (const float*)d_in[13];
  float* out = (float*)d_out;

  size_t proj_smem = (size_t)(EE * 256 + EE * 16) * 4;        // 108800
  size_t lstm_smem = (size_t)(256 * 128) * 4 + 256 * 16 * 8;  // 131072 + 32768 = 163840
  cudaFuncSetAttribute(proj_kernel, cudaFuncAttributeMaxDynamicSharedMemorySize, (int)proj_smem);
  cudaFuncSetAttribute(lstm_kernel, cudaFuncAttributeMaxDynamicSharedMemorySize, (int)lstm_smem);

  proj_kernel<<<3000, 256, proj_smem>>>(emb, Wih_f, b_f, Wih_b, b_b);
  lstm_kernel<<<NBLK, 256, lstm_smem>>>(data, Whh_f, Whh_b);
  emis_kernel<<<SS, 128>>>(mlpW, mlpb);
  vit_kernel<<<BB, 32>>>(data, st, tr, et, out);
}